// round 14
// baseline (speedup 1.0000x reference)
#include <cuda_runtime.h>
#include <cuda_bf16.h>
#include <cstdint>
#include <math.h>

#define NN_MAX 100000
#define NE_MAX 3200000
#define HIDC   256
#define INFEAT 128

// ---------------- scratch (static __device__ globals; no allocation) ----------
__device__ float g_h  [(size_t)NN_MAX * HIDC];
__device__ float g_f  [(size_t)NN_MAX * HIDC];
__device__ __nv_bfloat16 g_hb [(size_t)NN_MAX * HIDC], g_hl [(size_t)NN_MAX * HIDC];
__device__ __nv_bfloat16 g_fhb[(size_t)NN_MAX * HIDC], g_fhl[(size_t)NN_MAX * HIDC];
__device__ __nv_bfloat16 g_mb [(size_t)NN_MAX * HIDC], g_ml [(size_t)NN_MAX * HIDC];
__device__ __nv_bfloat16 g_xb [(size_t)NN_MAX * INFEAT], g_xl [(size_t)NN_MAX * INFEAT];
// fragment-ordered weights: [K/16][N/8][32 lanes][2 regs] as uint2 per lane
__device__ uint2 g_wih[4096],  g_wil[4096];
__device__ uint2 g_wfh[16384], g_wfl[16384];
__device__ uint2 g_ufh[16384], g_ufl[16384];
__device__ uint2 g_whh[16384], g_whl[16384];
__device__ uint2 g_uhh[16384], g_uhl[16384];
// CSR (grouped by destination)
__device__ int g_icnt[NN_MAX];
__device__ int g_off [NN_MAX + 1];
__device__ int g_pos [NN_MAX];
__device__ int g_csrc[NE_MAX];
__device__ float g_sum[HIDC];

__device__ __forceinline__ uint32_t smem_to_u32(const void* p) {
    uint32_t a;
    asm("{ .reg .u64 t; cvta.to.shared.u64 t, %1; cvt.u32.u64 %0, t; }" : "=r"(a) : "l"(p));
    return a;
}

__device__ __forceinline__ void split_pair(float a, float b,
                                           __nv_bfloat162& hi, __nv_bfloat162& lo) {
    __nv_bfloat16 h0 = __float2bfloat16_rn(a);
    __nv_bfloat16 h1 = __float2bfloat16_rn(b);
    hi = __nv_bfloat162(h0, h1);
    lo = __nv_bfloat162(__float2bfloat16_rn(a - __bfloat162float(h0)),
                        __float2bfloat16_rn(b - __bfloat162float(h1)));
}

// ---------------- CSR build ----------------
__global__ void count_kernel(const int* __restrict__ dst, int nE) {
    int i = blockIdx.x * blockDim.x + threadIdx.x;
    if (i < nE) atomicAdd(&g_icnt[dst[i]], 1);
}

__global__ void scan_kernel(int nN) {
    __shared__ int part[1024];
    int t = threadIdx.x;
    int chunk = (nN + 1023) / 1024;
    int b = t * chunk;
    int e = min(b + chunk, nN);
    int s = 0;
    for (int i = b; i < e; ++i) s += g_icnt[i];
    part[t] = s;
    __syncthreads();
    for (int d = 1; d < 1024; d <<= 1) {
        int v = (t >= d) ? part[t - d] : 0;
        __syncthreads();
        part[t] += v;
        __syncthreads();
    }
    int run = part[t] - s;
    for (int i = b; i < e; ++i) {
        g_off[i] = run;
        g_pos[i] = run;
        run += g_icnt[i];
    }
    if (t == 1023) g_off[nN] = part[1023];
}

__global__ void fill_kernel(const int* __restrict__ src,
                            const int* __restrict__ dst, int nE) {
    int i = blockIdx.x * blockDim.x + threadIdx.x;
    if (i < nE) {
        int p = atomicAdd(&g_pos[dst[i]], 1);
        g_csrc[p] = src[i];
    }
}

// ---------------- pull-mode aggregation: one warp per destination node -------
__global__ __launch_bounds__(256)
void gather_kernel(int nN) {
    int w = (blockIdx.x * blockDim.x + threadIdx.x) >> 5;
    int lane = threadIdx.x & 31;
    if (w >= nN) return;
    int beg = g_off[w], end = g_off[w + 1];
    float acc[8] = {0.f, 0.f, 0.f, 0.f, 0.f, 0.f, 0.f, 0.f};
    int e = beg;
    for (; e + 1 < end; e += 2) {
        int s0 = g_csrc[e];
        int s1 = g_csrc[e + 1];
        const float4* r0 = reinterpret_cast<const float4*>(g_h + (size_t)s0 * HIDC) + lane * 2;
        const float4* r1 = reinterpret_cast<const float4*>(g_h + (size_t)s1 * HIDC) + lane * 2;
        float4 a0 = r0[0], a1 = r0[1];
        float4 b0 = r1[0], b1 = r1[1];
        acc[0] += a0.x + b0.x; acc[1] += a0.y + b0.y;
        acc[2] += a0.z + b0.z; acc[3] += a0.w + b0.w;
        acc[4] += a1.x + b1.x; acc[5] += a1.y + b1.y;
        acc[6] += a1.z + b1.z; acc[7] += a1.w + b1.w;
    }
    if (e < end) {
        int s0 = g_csrc[e];
        const float4* r0 = reinterpret_cast<const float4*>(g_h + (size_t)s0 * HIDC) + lane * 2;
        float4 a0 = r0[0], a1 = r0[1];
        acc[0] += a0.x; acc[1] += a0.y; acc[2] += a0.z; acc[3] += a0.w;
        acc[4] += a1.x; acc[5] += a1.y; acc[6] += a1.z; acc[7] += a1.w;
    }
    float inv = 1.f / fmaxf((float)(end - beg), 1.f);
    __nv_bfloat162 hi[4], lo[4];
    split_pair(acc[0] * inv, acc[1] * inv, hi[0], lo[0]);
    split_pair(acc[2] * inv, acc[3] * inv, hi[1], lo[1]);
    split_pair(acc[4] * inv, acc[5] * inv, hi[2], lo[2]);
    split_pair(acc[6] * inv, acc[7] * inv, hi[3], lo[3]);
    size_t o = (size_t)w * HIDC + lane * 8;
    *reinterpret_cast<uint4*>(g_mb + o) = *reinterpret_cast<const uint4*>(hi);
    *reinterpret_cast<uint4*>(g_ml + o) = *reinterpret_cast<const uint4*>(lo);
}

// ---------------- consolidated prep: 5 weight-frag sections + x split --------
__device__ void wfrag_one(const float* W, uint2* hi, uint2* lo, int N, int K, int i) {
    int lane = i & 31;
    int rest = i >> 5;
    int n8 = rest % (N / 8);
    int k16 = rest / (N / 8);
    int n = n8 * 8 + (lane >> 2);
    uint32_t rh[2], rl[2];
#pragma unroll
    for (int reg = 0; reg < 2; ++reg) {
        int k = k16 * 16 + reg * 8 + (lane & 3) * 2;
        float w0 = W[(size_t)n * K + k];
        float w1 = W[(size_t)n * K + k + 1];
        __nv_bfloat16 h0 = __float2bfloat16_rn(w0);
        __nv_bfloat16 h1 = __float2bfloat16_rn(w1);
        rh[reg] = ((uint32_t)__bfloat16_as_ushort(h1) << 16) | __bfloat16_as_ushort(h0);
        rl[reg] = ((uint32_t)__bfloat16_as_ushort(__float2bfloat16_rn(w1 - __bfloat162float(h1))) << 16)
                | __bfloat16_as_ushort(__float2bfloat16_rn(w0 - __bfloat162float(h0)));
    }
    hi[i] = make_uint2(rh[0], rh[1]);
    lo[i] = make_uint2(rl[0], rl[1]);
}

__global__ void prep_kernel(const float* __restrict__ x,
                            const float* __restrict__ Win, const float* __restrict__ Wf,
                            const float* __restrict__ Uf, const float* __restrict__ Wh,
                            const float* __restrict__ Uh, int nx) {
    int i = blockIdx.x * blockDim.x + threadIdx.x;
    if (i < 4096) { wfrag_one(Win, g_wih, g_wil, 128, 128, i); return; }
    i -= 4096;
    if (i < 16384) { wfrag_one(Wf, g_wfh, g_wfl, 256, 256, i); return; }
    i -= 16384;
    if (i < 16384) { wfrag_one(Uf, g_ufh, g_ufl, 256, 256, i); return; }
    i -= 16384;
    if (i < 16384) { wfrag_one(Wh, g_whh, g_whl, 256, 256, i); return; }
    i -= 16384;
    if (i < 16384) { wfrag_one(Uh, g_uhh, g_uhl, 256, 256, i); return; }
    i -= 16384;
    int j = i * 2;
    if (j < nx) {
        __nv_bfloat162 hi, lo;
        split_pair(x[j], x[j + 1], hi, lo);
        *reinterpret_cast<__nv_bfloat162*>(g_xb + j) = hi;
        *reinterpret_cast<__nv_bfloat162*>(g_xl + j) = lo;
    }
}

// ---------------- HMMA dual-GEMM (R10 skeleton, 2x4 warp tiling) --------------
// C = sum_pass [ Ah*(Wh+Wl) + Al*Wh ]
// 8 warps: wm=warp>>2 (64 rows of 16x4), wn=warp&3 (32 cols of 8x4)
// -> B-fragment global loads deduped 2x vs 4x2 tiling
__device__ __forceinline__ void mma16816(float c[4], const uint32_t a[4], uint2 b) {
    asm volatile("mma.sync.aligned.m16n8k16.row.col.f32.bf16.bf16.f32 "
                 "{%0,%1,%2,%3}, {%4,%5,%6,%7}, {%8,%9}, {%0,%1,%2,%3};"
                 : "+f"(c[0]), "+f"(c[1]), "+f"(c[2]), "+f"(c[3])
                 : "r"(a[0]), "r"(a[1]), "r"(a[2]), "r"(a[3]), "r"(b.x), "r"(b.y));
}

__global__ __launch_bounds__(256)
void gemm_mma(const __nv_bfloat16* __restrict__ A0h, const __nv_bfloat16* __restrict__ A0l,
              const uint2* __restrict__ W0h, const uint2* __restrict__ W0l, int K0,
              const __nv_bfloat16* __restrict__ A1h, const __nv_bfloat16* __restrict__ A1l,
              const uint2* __restrict__ W1h, const uint2* __restrict__ W1l, int K1,
              int NT, const float* __restrict__ bias, int M, int mode,
              const float* __restrict__ f_in, const float* __restrict__ h_in,
              float* __restrict__ out0,
              __nv_bfloat16* __restrict__ outh, __nv_bfloat16* __restrict__ outl) {
    __shared__ __align__(16) __nv_bfloat16 Ash[128 * 32];
    __shared__ __align__(16) __nv_bfloat16 Asl[128 * 32];

    const int tid = threadIdx.x, lane = tid & 31, warp = tid >> 5;
    const int wm = warp >> 2;          // 0..1 : 64 rows
    const int wn = warp & 3;           // 0..3 : 32 cols
    const int m0 = blockIdx.x * 128;
    const int nblk = blockIdx.y;
    const int nt0 = nblk * 16 + wn * 4;
    const uint32_t sbh = smem_to_u32(Ash);
    const uint32_t sbl = smem_to_u32(Asl);

    float c[4][4][4];
#pragma unroll
    for (int i = 0; i < 4; ++i)
#pragma unroll
        for (int j = 0; j < 4; ++j)
#pragma unroll
            for (int k = 0; k < 4; ++k) c[i][j][k] = 0.f;

    const int lr = lane & 7, lmat = lane >> 3;
    const int lrow_off = (lmat & 1) * 8 + lr;
    const int lcu_off = lmat >> 1;

    for (int pass = 0; pass < 2; ++pass) {
        const __nv_bfloat16* Ah = pass ? A1h : A0h;
        if (!Ah) break;
        const __nv_bfloat16* Al = pass ? A1l : A0l;
        const uint2* Wh = pass ? W1h : W0h;
        const uint2* Wl = pass ? W1l : W0l;
        const int K = pass ? K1 : K0;

        for (int kc = 0; kc < K / 32; ++kc) {
            __syncthreads();
#pragma unroll
            for (int i = 0; i < 2; ++i) {
                int s = tid + i * 256;
                int row = s >> 2, cu = s & 3;
                uint32_t soff = row * 64 + ((cu ^ ((row >> 1) & 3)) << 4);
                uint4 vh = make_uint4(0, 0, 0, 0), vl = make_uint4(0, 0, 0, 0);
                if (m0 + row < M) {
                    size_t go = (size_t)(m0 + row) * K + kc * 32 + cu * 8;
                    vh = *reinterpret_cast<const uint4*>(Ah + go);
                    vl = *reinterpret_cast<const uint4*>(Al + go);
                }
                *reinterpret_cast<uint4*>(reinterpret_cast<char*>(Ash) + soff) = vh;
                *reinterpret_cast<uint4*>(reinterpret_cast<char*>(Asl) + soff) = vl;
            }
            __syncthreads();

#pragma unroll
            for (int k16 = 0; k16 < 2; ++k16) {
                uint32_t ah[4][4], al[4][4];
#pragma unroll
                for (int mt = 0; mt < 4; ++mt) {
                    int row = wm * 64 + mt * 16 + lrow_off;
                    int cu = k16 * 2 + lcu_off;
                    uint32_t soff = row * 64 + ((cu ^ ((row >> 1) & 3)) << 4);
                    asm volatile("ldmatrix.sync.aligned.m8n8.x4.shared.b16 {%0,%1,%2,%3}, [%4];"
                                 : "=r"(ah[mt][0]), "=r"(ah[mt][1]), "=r"(ah[mt][2]), "=r"(ah[mt][3])
                                 : "r"(sbh + soff));
                    asm volatile("ldmatrix.sync.aligned.m8n8.x4.shared.b16 {%0,%1,%2,%3}, [%4];"
                                 : "=r"(al[mt][0]), "=r"(al[mt][1]), "=r"(al[mt][2]), "=r"(al[mt][3])
                                 : "r"(sbl + soff));
                }
                int gk16 = kc * 2 + k16;
                const uint2* bhp = Wh + ((size_t)gk16 * NT + nt0) * 32 + lane;
                const uint2* blp = Wl + ((size_t)gk16 * NT + nt0) * 32 + lane;
#pragma unroll
                for (int nt = 0; nt < 4; ++nt) {
                    uint2 bhv = bhp[nt * 32];
                    uint2 blv = blp[nt * 32];
#pragma unroll
                    for (int mt = 0; mt < 4; ++mt) {
                        mma16816(c[mt][nt], ah[mt], bhv);
                        mma16816(c[mt][nt], ah[mt], blv);
                        mma16816(c[mt][nt], al[mt], bhv);
                    }
                }
            }
        }
    }

    // epilogue
#pragma unroll
    for (int mt = 0; mt < 4; ++mt) {
#pragma unroll
        for (int half = 0; half < 2; ++half) {
            int row = m0 + wm * 64 + mt * 16 + (lane >> 2) + half * 8;
            if (row >= M) continue;
            size_t ro = (size_t)row * HIDC;
#pragma unroll
            for (int nt = 0; nt < 4; ++nt) {
                int col = nblk * 128 + wn * 32 + nt * 8 + (lane & 3) * 2;
                float v0 = c[mt][nt][half * 2 + 0];
                float v1 = c[mt][nt][half * 2 + 1];
                float2 b = *reinterpret_cast<const float2*>(bias + col);
                v0 += b.x; v1 += b.y;
                __nv_bfloat162 hi, lo;
                if (mode == 0) {
                    float o0 = fmaxf(v0, 0.f), o1 = fmaxf(v1, 0.f);
                    *reinterpret_cast<float2*>(out0 + ro + col) = make_float2(o0, o1);
                    split_pair(o0, o1, hi, lo);
                } else if (mode == 1) {
                    float f0 = 1.f / (1.f + expf(-v0));
                    float f1 = 1.f / (1.f + expf(-v1));
                    float2 h = *reinterpret_cast<const float2*>(h_in + ro + col);
                    *reinterpret_cast<float2*>(out0 + ro + col) = make_float2(f0, f1);
                    split_pair(f0 * h.x, f1 * h.y, hi, lo);
                } else {
                    float t0 = tanhf(v0), t1 = tanhf(v1);
                    float2 f = *reinterpret_cast<const float2*>(f_in + ro + col);
                    float2 h = *reinterpret_cast<const float2*>(h_in + ro + col);
                    float o0 = (1.f - f.x) * h.x + f.x * t0;
                    float o1 = (1.f - f.y) * h.y + f.y * t1;
                    *reinterpret_cast<float2*>(out0 + ro + col) = make_float2(o0, o1);
                    split_pair(o0, o1, hi, lo);
                }
                *reinterpret_cast<__nv_bfloat162*>(outh + ro + col) = hi;
                *reinterpret_cast<__nv_bfloat162*>(outl + ro + col) = lo;
            }
        }
    }
}

// ---------------- readout ----------------
__global__ void colsum_kernel(int nN) {
    int t = threadIdx.x;
    float acc = 0.f;
    for (int r = blockIdx.x; r < nN; r += gridDim.x)
        acc += g_h[(size_t)r * HIDC + t];
    atomicAdd(&g_sum[t], acc);
}
__global__ void final_kernel(const float* __restrict__ Wp, const float* __restrict__ bp,
                             float* __restrict__ out, int nN) {
    __shared__ float sh[HIDC];
    int t = threadIdx.x;
    sh[t] = g_sum[t] * (1.0f / (float)nN) * Wp[t];
    __syncthreads();
    for (int s = 128; s > 0; s >>= 1) {
        if (t < s) sh[t] += sh[t + s];
        __syncthreads();
    }
    if (t == 0) out[0] = sh[0] + bp[0];
}

// ---------------- launch ----------------
extern "C" void kernel_launch(void* const* d_in, const int* in_sizes, int n_in,
                              void* d_out, int out_size) {
    const float* x      = (const float*)d_in[0];
    const int*   ei     = (const int*)d_in[1];   // int32 (jax x64 disabled)
    const float* b_in   = (const float*)d_in[3];
    const float* b_f    = (const float*)d_in[6];
    const float* b_h    = (const float*)d_in[9];
    const float* W_pred = (const float*)d_in[10];
    const float* b_pred = (const float*)d_in[11];
    float* out = (float*)d_out;

    int nN = in_sizes[0] / INFEAT;   // 100000
    int nE = in_sizes[1] / 2;        // 3200000
    const int* srcp = ei;
    const int* dstp = ei + nE;

    void *ph, *pf, *phb, *phl, *pfhb, *pfhl, *pmb, *pml, *pxb, *pxl, *picnt, *psum;
    void *pwih, *pwil, *pwfh, *pwfl, *pufh, *pufl, *pwhh, *pwhl, *puhh, *puhl;
    cudaGetSymbolAddress(&ph, g_h);
    cudaGetSymbolAddress(&pf, g_f);
    cudaGetSymbolAddress(&phb, g_hb);   cudaGetSymbolAddress(&phl, g_hl);
    cudaGetSymbolAddress(&pfhb, g_fhb); cudaGetSymbolAddress(&pfhl, g_fhl);
    cudaGetSymbolAddress(&pmb, g_mb);   cudaGetSymbolAddress(&pml, g_ml);
    cudaGetSymbolAddress(&pxb, g_xb);   cudaGetSymbolAddress(&pxl, g_xl);
    cudaGetSymbolAddress(&picnt, g_icnt);
    cudaGetSymbolAddress(&psum, g_sum);
    cudaGetSymbolAddress(&pwih, g_wih); cudaGetSymbolAddress(&pwil, g_wil);
    cudaGetSymbolAddress(&pwfh, g_wfh); cudaGetSymbolAddress(&pwfl, g_wfl);
    cudaGetSymbolAddress(&pufh, g_ufh); cudaGetSymbolAddress(&pufl, g_ufl);
    cudaGetSymbolAddress(&pwhh, g_whh); cudaGetSymbolAddress(&pwhl, g_whl);
    cudaGetSymbolAddress(&puhh, g_uhh); cudaGetSymbolAddress(&puhl, g_uhl);
    float* hbuf = (float*)ph;
    float* fbuf = (float*)pf;
    __nv_bfloat16 *hb = (__nv_bfloat16*)phb,  *hl = (__nv_bfloat16*)phl;
    __nv_bfloat16 *fhb = (__nv_bfloat16*)pfhb, *fhl = (__nv_bfloat16*)pfhl;
    __nv_bfloat16 *mb = (__nv_bfloat16*)pmb,  *ml = (__nv_bfloat16*)pml;

    size_t hbytes = (size_t)nN * HIDC * sizeof(float);
    size_t bbytes = (size_t)nN * HIDC * sizeof(__nv_bfloat16);

    // init (R10-style: memsets are cheap, ~35us total)
    cudaMemsetAsync(ph, 0, hbytes);
    cudaMemsetAsync(phb, 0, bbytes);
    cudaMemsetAsync(phl, 0, bbytes);
    cudaMemsetAsync(picnt, 0, (size_t)nN * sizeof(int));

    int prep_threads = 4096 + 4 * 16384 + nN * INFEAT / 2;
    prep_kernel<<<(prep_threads + 255) / 256, 256>>>(
        x, (const float*)d_in[2], (const float*)d_in[4], (const float*)d_in[5],
        (const float*)d_in[7], (const float*)d_in[8], nN * INFEAT);

    // CSR build
    count_kernel<<<(nE + 255) / 256, 256>>>(dstp, nE);
    scan_kernel<<<1, 1024>>>(nN);
    fill_kernel<<<(nE + 255) / 256, 256>>>(srcp, dstp, nE);

    int gmx = (nN + 127) / 128;
    // encode: h = relu(x @ W_in^T + b_in), cols 0..127 (pad cols stay 0)
    gemm_mma<<<dim3(gmx, 1), 256>>>(
        (__nv_bfloat16*)pxb, (__nv_bfloat16*)pxl, (uint2*)pwih, (uint2*)pwil, INFEAT,
        nullptr, nullptr, nullptr, nullptr, 0, 16,
        b_in, nN, 0, nullptr, nullptr, hbuf, hb, hl);

    int gather_blocks = (nN + 7) / 8;
    for (int step = 0; step < 4; ++step) {
        gather_kernel<<<gather_blocks, 256>>>(nN);
        gemm_mma<<<dim3(gmx, 2), 256>>>(
            mb, ml, (uint2*)pwfh, (uint2*)pwfl, HIDC,
            hb, hl, (uint2*)pufh, (uint2*)pufl, HIDC, 32,
            b_f, nN, 1, nullptr, hbuf, fbuf, fhb, fhl);
        gemm_mma<<<dim3(gmx, 2), 256>>>(
            mb, ml, (uint2*)pwhh, (uint2*)pwhl, HIDC,
            fhb, fhl, (uint2*)puhh, (uint2*)puhl, HIDC, 32,
            b_h, nN, 2, fbuf, hbuf, hbuf, hb, hl);
    }

    cudaMemsetAsync(psum, 0, HIDC * sizeof(float));
    colsum_kernel<<<1024, 256>>>(nN);
    final_kernel<<<1, 256>>>(W_pred, b_pred, out, nN);
}

// round 15
// speedup vs baseline: 1.4209x; 1.4209x over previous
#include <cuda_runtime.h>
#include <cuda_bf16.h>
#include <cstdint>
#include <math.h>

#define NN_MAX 100000
#define NE_MAX 3200000
#define HIDC   256
#define INFEAT 128

// ---------------- scratch (static __device__ globals; no allocation) ----------
__device__ float g_h  [(size_t)NN_MAX * HIDC];
__device__ float g_f  [(size_t)NN_MAX * HIDC];
__device__ __nv_bfloat16 g_hb [(size_t)NN_MAX * HIDC], g_hl [(size_t)NN_MAX * HIDC];
__device__ __nv_bfloat16 g_fhb[(size_t)NN_MAX * HIDC], g_fhl[(size_t)NN_MAX * HIDC];
__device__ __nv_bfloat16 g_mb [(size_t)NN_MAX * HIDC], g_ml [(size_t)NN_MAX * HIDC];
__device__ __nv_bfloat16 g_xb [(size_t)NN_MAX * INFEAT], g_xl [(size_t)NN_MAX * INFEAT];
// fragment-ordered weights: [K/16][N/8][32 lanes][2 regs] as uint2 per lane
__device__ uint2 g_wih[4096],  g_wil[4096];
__device__ uint2 g_wfh[16384], g_wfl[16384];
__device__ uint2 g_ufh[16384], g_ufl[16384];
__device__ uint2 g_whh[16384], g_whl[16384];
__device__ uint2 g_uhh[16384], g_uhl[16384];
// CSR (grouped by destination)
__device__ int g_icnt[NN_MAX];
__device__ int g_off [NN_MAX + 1];
__device__ int g_pos [NN_MAX];
__device__ int g_csrc[NE_MAX];
__device__ float g_sum[HIDC];

__device__ __forceinline__ uint32_t smem_to_u32(const void* p) {
    uint32_t a;
    asm("{ .reg .u64 t; cvta.to.shared.u64 t, %1; cvt.u32.u64 %0, t; }" : "=r"(a) : "l"(p));
    return a;
}

__device__ __forceinline__ void split_pair(float a, float b,
                                           __nv_bfloat162& hi, __nv_bfloat162& lo) {
    __nv_bfloat16 h0 = __float2bfloat16_rn(a);
    __nv_bfloat16 h1 = __float2bfloat16_rn(b);
    hi = __nv_bfloat162(h0, h1);
    lo = __nv_bfloat162(__float2bfloat16_rn(a - __bfloat162float(h0)),
                        __float2bfloat16_rn(b - __bfloat162float(h1)));
}

// ---------------- CSR build ----------------
__global__ void count_kernel(const int* __restrict__ dst, int nE) {
    int i = blockIdx.x * blockDim.x + threadIdx.x;
    if (i < nE) atomicAdd(&g_icnt[dst[i]], 1);
}

__global__ void scan_kernel(int nN) {
    __shared__ int part[1024];
    int t = threadIdx.x;
    int chunk = (nN + 1023) / 1024;
    int b = t * chunk;
    int e = min(b + chunk, nN);
    int s = 0;
    for (int i = b; i < e; ++i) s += g_icnt[i];
    part[t] = s;
    __syncthreads();
    for (int d = 1; d < 1024; d <<= 1) {
        int v = (t >= d) ? part[t - d] : 0;
        __syncthreads();
        part[t] += v;
        __syncthreads();
    }
    int run = part[t] - s;
    for (int i = b; i < e; ++i) {
        g_off[i] = run;
        g_pos[i] = run;
        run += g_icnt[i];
    }
    if (t == 1023) g_off[nN] = part[1023];
}

__global__ void fill_kernel(const int* __restrict__ src,
                            const int* __restrict__ dst, int nE) {
    int i = blockIdx.x * blockDim.x + threadIdx.x;
    if (i < nE) {
        int p = atomicAdd(&g_pos[dst[i]], 1);
        g_csrc[p] = src[i];
    }
}

// ---------------- pull-mode aggregation: TWO warps per destination node ------
// warp handles 128 contiguous features (half a row); 4-neighbor unroll for MLP
__global__ __launch_bounds__(256)
void gather_kernel(int nN) {
    int w = (blockIdx.x * blockDim.x + threadIdx.x) >> 5;
    int lane = threadIdx.x & 31;
    int node = w >> 1;
    int half = w & 1;
    if (node >= nN) return;
    int beg = g_off[node], end = g_off[node + 1];
    size_t foff = (size_t)half * 128 + lane * 4;   // feature offset within row
    float4 acc = make_float4(0.f, 0.f, 0.f, 0.f);
    int e = beg;
    for (; e + 3 < end; e += 4) {
        int s0 = g_csrc[e], s1 = g_csrc[e + 1], s2 = g_csrc[e + 2], s3 = g_csrc[e + 3];
        float4 a = *reinterpret_cast<const float4*>(g_h + (size_t)s0 * HIDC + foff);
        float4 b = *reinterpret_cast<const float4*>(g_h + (size_t)s1 * HIDC + foff);
        float4 c = *reinterpret_cast<const float4*>(g_h + (size_t)s2 * HIDC + foff);
        float4 d = *reinterpret_cast<const float4*>(g_h + (size_t)s3 * HIDC + foff);
        acc.x += (a.x + b.x) + (c.x + d.x);
        acc.y += (a.y + b.y) + (c.y + d.y);
        acc.z += (a.z + b.z) + (c.z + d.z);
        acc.w += (a.w + b.w) + (c.w + d.w);
    }
    for (; e < end; ++e) {
        int s0 = g_csrc[e];
        float4 a = *reinterpret_cast<const float4*>(g_h + (size_t)s0 * HIDC + foff);
        acc.x += a.x; acc.y += a.y; acc.z += a.z; acc.w += a.w;
    }
    float inv = 1.f / fmaxf((float)(end - beg), 1.f);
    __nv_bfloat162 hi[2], lo[2];
    split_pair(acc.x * inv, acc.y * inv, hi[0], lo[0]);
    split_pair(acc.z * inv, acc.w * inv, hi[1], lo[1]);
    size_t o = (size_t)node * HIDC + foff;
    *reinterpret_cast<uint2*>(g_mb + o) = *reinterpret_cast<const uint2*>(hi);
    *reinterpret_cast<uint2*>(g_ml + o) = *reinterpret_cast<const uint2*>(lo);
}

// ---------------- consolidated prep: 5 weight-frag sections + x split --------
__device__ void wfrag_one(const float* W, uint2* hi, uint2* lo, int N, int K, int i) {
    int lane = i & 31;
    int rest = i >> 5;
    int n8 = rest % (N / 8);
    int k16 = rest / (N / 8);
    int n = n8 * 8 + (lane >> 2);
    uint32_t rh[2], rl[2];
#pragma unroll
    for (int reg = 0; reg < 2; ++reg) {
        int k = k16 * 16 + reg * 8 + (lane & 3) * 2;
        float w0 = W[(size_t)n * K + k];
        float w1 = W[(size_t)n * K + k + 1];
        __nv_bfloat16 h0 = __float2bfloat16_rn(w0);
        __nv_bfloat16 h1 = __float2bfloat16_rn(w1);
        rh[reg] = ((uint32_t)__bfloat16_as_ushort(h1) << 16) | __bfloat16_as_ushort(h0);
        rl[reg] = ((uint32_t)__bfloat16_as_ushort(__float2bfloat16_rn(w1 - __bfloat162float(h1))) << 16)
                | __bfloat16_as_ushort(__float2bfloat16_rn(w0 - __bfloat162float(h0)));
    }
    hi[i] = make_uint2(rh[0], rh[1]);
    lo[i] = make_uint2(rl[0], rl[1]);
}

__global__ void prep_kernel(const float* __restrict__ x,
                            const float* __restrict__ Win, const float* __restrict__ Wf,
                            const float* __restrict__ Uf, const float* __restrict__ Wh,
                            const float* __restrict__ Uh, int nx) {
    int i = blockIdx.x * blockDim.x + threadIdx.x;
    if (i < 4096) { wfrag_one(Win, g_wih, g_wil, 128, 128, i); return; }
    i -= 4096;
    if (i < 16384) { wfrag_one(Wf, g_wfh, g_wfl, 256, 256, i); return; }
    i -= 16384;
    if (i < 16384) { wfrag_one(Uf, g_ufh, g_ufl, 256, 256, i); return; }
    i -= 16384;
    if (i < 16384) { wfrag_one(Wh, g_whh, g_whl, 256, 256, i); return; }
    i -= 16384;
    if (i < 16384) { wfrag_one(Uh, g_uhh, g_uhl, 256, 256, i); return; }
    i -= 16384;
    int j = i * 2;
    if (j < nx) {
        __nv_bfloat162 hi, lo;
        split_pair(x[j], x[j + 1], hi, lo);
        *reinterpret_cast<__nv_bfloat162*>(g_xb + j) = hi;
        *reinterpret_cast<__nv_bfloat162*>(g_xl + j) = lo;
    }
}

// ---------------- HMMA dual-GEMM (R10 verbatim: 4x2 warp tiling) --------------
// C = sum_pass [ Ah*(Wh+Wl) + Al*Wh ]
__device__ __forceinline__ void mma16816(float c[4], const uint32_t a[4], uint2 b) {
    asm volatile("mma.sync.aligned.m16n8k16.row.col.f32.bf16.bf16.f32 "
                 "{%0,%1,%2,%3}, {%4,%5,%6,%7}, {%8,%9}, {%0,%1,%2,%3};"
                 : "+f"(c[0]), "+f"(c[1]), "+f"(c[2]), "+f"(c[3])
                 : "r"(a[0]), "r"(a[1]), "r"(a[2]), "r"(a[3]), "r"(b.x), "r"(b.y));
}

__global__ __launch_bounds__(256)
void gemm_mma(const __nv_bfloat16* __restrict__ A0h, const __nv_bfloat16* __restrict__ A0l,
              const uint2* __restrict__ W0h, const uint2* __restrict__ W0l, int K0,
              const __nv_bfloat16* __restrict__ A1h, const __nv_bfloat16* __restrict__ A1l,
              const uint2* __restrict__ W1h, const uint2* __restrict__ W1l, int K1,
              int NT, const float* __restrict__ bias, int M, int mode,
              const float* __restrict__ f_in, const float* __restrict__ h_in,
              float* __restrict__ out0,
              __nv_bfloat16* __restrict__ outh, __nv_bfloat16* __restrict__ outl) {
    __shared__ __align__(16) __nv_bfloat16 Ash[128 * 32];
    __shared__ __align__(16) __nv_bfloat16 Asl[128 * 32];

    const int tid = threadIdx.x, lane = tid & 31, warp = tid >> 5;
    const int wm = warp & 3, wn = warp >> 2;
    const int m0 = blockIdx.x * 128;
    const int nblk = blockIdx.y;
    const int nt0 = nblk * 16 + wn * 8;
    const uint32_t sbh = smem_to_u32(Ash);
    const uint32_t sbl = smem_to_u32(Asl);

    float c[2][8][4];
#pragma unroll
    for (int i = 0; i < 2; ++i)
#pragma unroll
        for (int j = 0; j < 8; ++j)
#pragma unroll
            for (int k = 0; k < 4; ++k) c[i][j][k] = 0.f;

    const int lr = lane & 7, lmat = lane >> 3;
    const int lrow_off = (lmat & 1) * 8 + lr;
    const int lcu_off = lmat >> 1;

    for (int pass = 0; pass < 2; ++pass) {
        const __nv_bfloat16* Ah = pass ? A1h : A0h;
        if (!Ah) break;
        const __nv_bfloat16* Al = pass ? A1l : A0l;
        const uint2* Wh = pass ? W1h : W0h;
        const uint2* Wl = pass ? W1l : W0l;
        const int K = pass ? K1 : K0;

        for (int kc = 0; kc < K / 32; ++kc) {
            __syncthreads();
#pragma unroll
            for (int i = 0; i < 2; ++i) {
                int s = tid + i * 256;
                int row = s >> 2, cu = s & 3;
                uint32_t soff = row * 64 + ((cu ^ ((row >> 1) & 3)) << 4);
                uint4 vh = make_uint4(0, 0, 0, 0), vl = make_uint4(0, 0, 0, 0);
                if (m0 + row < M) {
                    size_t go = (size_t)(m0 + row) * K + kc * 32 + cu * 8;
                    vh = *reinterpret_cast<const uint4*>(Ah + go);
                    vl = *reinterpret_cast<const uint4*>(Al + go);
                }
                *reinterpret_cast<uint4*>(reinterpret_cast<char*>(Ash) + soff) = vh;
                *reinterpret_cast<uint4*>(reinterpret_cast<char*>(Asl) + soff) = vl;
            }
            __syncthreads();

#pragma unroll
            for (int k16 = 0; k16 < 2; ++k16) {
                uint32_t ah[2][4], al[2][4];
#pragma unroll
                for (int mt = 0; mt < 2; ++mt) {
                    int row = wm * 32 + mt * 16 + lrow_off;
                    int cu = k16 * 2 + lcu_off;
                    uint32_t soff = row * 64 + ((cu ^ ((row >> 1) & 3)) << 4);
                    asm volatile("ldmatrix.sync.aligned.m8n8.x4.shared.b16 {%0,%1,%2,%3}, [%4];"
                                 : "=r"(ah[mt][0]), "=r"(ah[mt][1]), "=r"(ah[mt][2]), "=r"(ah[mt][3])
                                 : "r"(sbh + soff));
                    asm volatile("ldmatrix.sync.aligned.m8n8.x4.shared.b16 {%0,%1,%2,%3}, [%4];"
                                 : "=r"(al[mt][0]), "=r"(al[mt][1]), "=r"(al[mt][2]), "=r"(al[mt][3])
                                 : "r"(sbl + soff));
                }
                int gk16 = kc * 2 + k16;
                const uint2* bhp = Wh + ((size_t)gk16 * NT + nt0) * 32 + lane;
                const uint2* blp = Wl + ((size_t)gk16 * NT + nt0) * 32 + lane;
#pragma unroll
                for (int nt = 0; nt < 8; ++nt) {
                    uint2 bhv = bhp[nt * 32];
                    uint2 blv = blp[nt * 32];
#pragma unroll
                    for (int mt = 0; mt < 2; ++mt) {
                        mma16816(c[mt][nt], ah[mt], bhv);
                        mma16816(c[mt][nt], ah[mt], blv);
                        mma16816(c[mt][nt], al[mt], bhv);
                    }
                }
            }
        }
    }

    // epilogue
#pragma unroll
    for (int mt = 0; mt < 2; ++mt) {
#pragma unroll
        for (int half = 0; half < 2; ++half) {
            int row = m0 + wm * 32 + mt * 16 + (lane >> 2) + half * 8;
            if (row >= M) continue;
            size_t ro = (size_t)row * HIDC;
#pragma unroll
            for (int nt = 0; nt < 8; ++nt) {
                int col = nblk * 128 + wn * 64 + nt * 8 + (lane & 3) * 2;
                float v0 = c[mt][nt][half * 2 + 0];
                float v1 = c[mt][nt][half * 2 + 1];
                float2 b = *reinterpret_cast<const float2*>(bias + col);
                v0 += b.x; v1 += b.y;
                __nv_bfloat162 hi, lo;
                if (mode == 0) {
                    float o0 = fmaxf(v0, 0.f), o1 = fmaxf(v1, 0.f);
                    *reinterpret_cast<float2*>(out0 + ro + col) = make_float2(o0, o1);
                    split_pair(o0, o1, hi, lo);
                } else if (mode == 1) {
                    float f0 = 1.f / (1.f + expf(-v0));
                    float f1 = 1.f / (1.f + expf(-v1));
                    float2 h = *reinterpret_cast<const float2*>(h_in + ro + col);
                    *reinterpret_cast<float2*>(out0 + ro + col) = make_float2(f0, f1);
                    split_pair(f0 * h.x, f1 * h.y, hi, lo);
                } else {
                    float t0 = tanhf(v0), t1 = tanhf(v1);
                    float2 f = *reinterpret_cast<const float2*>(f_in + ro + col);
                    float2 h = *reinterpret_cast<const float2*>(h_in + ro + col);
                    float o0 = (1.f - f.x) * h.x + f.x * t0;
                    float o1 = (1.f - f.y) * h.y + f.y * t1;
                    *reinterpret_cast<float2*>(out0 + ro + col) = make_float2(o0, o1);
                    split_pair(o0, o1, hi, lo);
                }
                *reinterpret_cast<__nv_bfloat162*>(outh + ro + col) = hi;
                *reinterpret_cast<__nv_bfloat162*>(outl + ro + col) = lo;
            }
        }
    }
}

// ---------------- readout ----------------
__global__ void colsum_kernel(int nN) {
    int t = threadIdx.x;
    float acc = 0.f;
    for (int r = blockIdx.x; r < nN; r += gridDim.x)
        acc += g_h[(size_t)r * HIDC + t];
    atomicAdd(&g_sum[t], acc);
}
__global__ void final_kernel(const float* __restrict__ Wp, const float* __restrict__ bp,
                             float* __restrict__ out, int nN) {
    __shared__ float sh[HIDC];
    int t = threadIdx.x;
    sh[t] = g_sum[t] * (1.0f / (float)nN) * Wp[t];
    __syncthreads();
    for (int s = 128; s > 0; s >>= 1) {
        if (t < s) sh[t] += sh[t + s];
        __syncthreads();
    }
    if (t == 0) out[0] = sh[0] + bp[0];
}

// ---------------- launch ----------------
extern "C" void kernel_launch(void* const* d_in, const int* in_sizes, int n_in,
                              void* d_out, int out_size) {
    const float* x      = (const float*)d_in[0];
    const int*   ei     = (const int*)d_in[1];   // int32 (jax x64 disabled)
    const float* b_in   = (const float*)d_in[3];
    const float* b_f    = (const float*)d_in[6];
    const float* b_h    = (const float*)d_in[9];
    const float* W_pred = (const float*)d_in[10];
    const float* b_pred = (const float*)d_in[11];
    float* out = (float*)d_out;

    int nN = in_sizes[0] / INFEAT;   // 100000
    int nE = in_sizes[1] / 2;        // 3200000
    const int* srcp = ei;
    const int* dstp = ei + nE;

    void *ph, *pf, *phb, *phl, *pfhb, *pfhl, *pmb, *pml, *pxb, *pxl, *picnt, *psum;
    void *pwih, *pwil, *pwfh, *pwfl, *pufh, *pufl, *pwhh, *pwhl, *puhh, *puhl;
    cudaGetSymbolAddress(&ph, g_h);
    cudaGetSymbolAddress(&pf, g_f);
    cudaGetSymbolAddress(&phb, g_hb);   cudaGetSymbolAddress(&phl, g_hl);
    cudaGetSymbolAddress(&pfhb, g_fhb); cudaGetSymbolAddress(&pfhl, g_fhl);
    cudaGetSymbolAddress(&pmb, g_mb);   cudaGetSymbolAddress(&pml, g_ml);
    cudaGetSymbolAddress(&pxb, g_xb);   cudaGetSymbolAddress(&pxl, g_xl);
    cudaGetSymbolAddress(&picnt, g_icnt);
    cudaGetSymbolAddress(&psum, g_sum);
    cudaGetSymbolAddress(&pwih, g_wih); cudaGetSymbolAddress(&pwil, g_wil);
    cudaGetSymbolAddress(&pwfh, g_wfh); cudaGetSymbolAddress(&pwfl, g_wfl);
    cudaGetSymbolAddress(&pufh, g_ufh); cudaGetSymbolAddress(&pufl, g_ufl);
    cudaGetSymbolAddress(&pwhh, g_whh); cudaGetSymbolAddress(&pwhl, g_whl);
    cudaGetSymbolAddress(&puhh, g_uhh); cudaGetSymbolAddress(&puhl, g_uhl);
    float* hbuf = (float*)ph;
    float* fbuf = (float*)pf;
    __nv_bfloat16 *hb = (__nv_bfloat16*)phb,  *hl = (__nv_bfloat16*)phl;
    __nv_bfloat16 *fhb = (__nv_bfloat16*)pfhb, *fhl = (__nv_bfloat16*)pfhl;
    __nv_bfloat16 *mb = (__nv_bfloat16*)pmb,  *ml = (__nv_bfloat16*)pml;

    size_t hbytes = (size_t)nN * HIDC * sizeof(float);
    size_t bbytes = (size_t)nN * HIDC * sizeof(__nv_bfloat16);

    cudaMemsetAsync(ph, 0, hbytes);
    cudaMemsetAsync(phb, 0, bbytes);
    cudaMemsetAsync(phl, 0, bbytes);
    cudaMemsetAsync(picnt, 0, (size_t)nN * sizeof(int));

    // launch 1: prep (weights + x split)
    int prep_threads = 4096 + 4 * 16384 + nN * INFEAT / 2;
    prep_kernel<<<(prep_threads + 255) / 256, 256>>>(
        x, (const float*)d_in[2], (const float*)d_in[4], (const float*)d_in[5],
        (const float*)d_in[7], (const float*)d_in[8], nN * INFEAT);

    int gmx = (nN + 127) / 128;
    // launch 2: encode GEMM (depends only on prep)
    gemm_mma<<<dim3(gmx, 1), 256>>>(
        (__nv_bfloat16*)pxb, (__nv_bfloat16*)pxl, (uint2*)pwih, (uint2*)pwil, INFEAT,
        nullptr, nullptr, nullptr, nullptr, 0, 16,
        b_in, nN, 0, nullptr, nullptr, hbuf, hb, hl);

    // launches 3-5: CSR build
    count_kernel<<<(nE + 255) / 256, 256>>>(dstp, nE);
    scan_kernel<<<1, 1024>>>(nN);
    fill_kernel<<<(nE + 255) / 256, 256>>>(srcp, dstp, nE);

    // launch 6+: mainloop (ncu -s 5 -c 1 captures the first gather)
    int gather_blocks = (2 * nN + 7) / 8;   // 2 warps/node, 8 warps/block
    for (int step = 0; step < 4; ++step) {
        gather_kernel<<<gather_blocks, 256>>>(nN);
        gemm_mma<<<dim3(gmx, 2), 256>>>(
            mb, ml, (uint2*)pwfh, (uint2*)pwfl, HIDC,
            hb, hl, (uint2*)pufh, (uint2*)pufl, HIDC, 32,
            b_f, nN, 1, nullptr, hbuf, fbuf, fhb, fhl);
        gemm_mma<<<dim3(gmx, 2), 256>>>(
            mb, ml, (uint2*)pwhh, (uint2*)pwhl, HIDC,
            fhb, fhl, (uint2*)puhh, (uint2*)puhl, HIDC, 32,
            b_h, nN, 2, fbuf, hbuf, hbuf, hb, hl);
    }

    cudaMemsetAsync(psum, 0, HIDC * sizeof(float));
    colsum_kernel<<<1024, 256>>>(nN);
    final_kernel<<<1, 256>>>(W_pred, b_pred, out, nN);
}

// round 17
// speedup vs baseline: 1.4474x; 1.0186x over previous
#include <cuda_runtime.h>
#include <cuda_bf16.h>
#include <cstdint>
#include <math.h>

#define NN_MAX 100000
#define NE_MAX 3200000
#define HIDC   256
#define INFEAT 128

// ---------------- scratch (static __device__ globals; no allocation) ----------
__device__ float g_h  [(size_t)NN_MAX * HIDC];
__device__ float g_f  [(size_t)NN_MAX * HIDC];
__device__ __nv_bfloat16 g_hb [(size_t)NN_MAX * HIDC], g_hl [(size_t)NN_MAX * HIDC];
__device__ __nv_bfloat16 g_fhb[(size_t)NN_MAX * HIDC], g_fhl[(size_t)NN_MAX * HIDC];
__device__ __nv_bfloat16 g_mb [(size_t)NN_MAX * HIDC], g_ml [(size_t)NN_MAX * HIDC];
__device__ __nv_bfloat16 g_xb [(size_t)NN_MAX * INFEAT], g_xl [(size_t)NN_MAX * INFEAT];
// fragment-ordered weights: [K/16][N/8][32 lanes][2 regs] as uint2 per lane
__device__ uint2 g_wih[4096],  g_wil[4096];
__device__ uint2 g_wfh[16384], g_wfl[16384];
__device__ uint2 g_ufh[16384], g_ufl[16384];
__device__ uint2 g_whh[16384], g_whl[16384];
__device__ uint2 g_uhh[16384], g_uhl[16384];
// CSR (grouped by destination)
__device__ int g_icnt[NN_MAX];
__device__ int g_off [NN_MAX + 1];
__device__ int g_pos [NN_MAX];
__device__ int g_csrc[NE_MAX];
__device__ int g_part[512];
__device__ float g_sum[HIDC];

__device__ __forceinline__ uint32_t smem_to_u32(const void* p) {
    uint32_t a;
    asm("{ .reg .u64 t; cvta.to.shared.u64 t, %1; cvt.u32.u64 %0, t; }" : "=r"(a) : "l"(p));
    return a;
}

__device__ __forceinline__ void split_pair(float a, float b,
                                           __nv_bfloat162& hi, __nv_bfloat162& lo) {
    __nv_bfloat16 h0 = __float2bfloat16_rn(a);
    __nv_bfloat16 h1 = __float2bfloat16_rn(b);
    hi = __nv_bfloat162(h0, h1);
    lo = __nv_bfloat162(__float2bfloat16_rn(a - __bfloat162float(h0)),
                        __float2bfloat16_rn(b - __bfloat162float(h1)));
}

// ---------------- CSR build ----------------
__global__ void count_kernel(const int* __restrict__ dst, int nE) {
    int i = blockIdx.x * blockDim.x + threadIdx.x;
    if (i < nE) atomicAdd(&g_icnt[dst[i]], 1);
}

// phase 1: per-block (256 elems) partial sums
__global__ void scan_partial(int nN) {
    __shared__ int wsum[8];
    int i = blockIdx.x * 256 + threadIdx.x;
    int lane = threadIdx.x & 31, wid = threadIdx.x >> 5;
    int v = (i < nN) ? g_icnt[i] : 0;
    int s = v;
#pragma unroll
    for (int d = 16; d > 0; d >>= 1) s += __shfl_down_sync(0xffffffffu, s, d);
    if (lane == 0) wsum[wid] = s;
    __syncthreads();
    if (threadIdx.x == 0) {
        int t = 0;
#pragma unroll
        for (int w = 0; w < 8; ++w) t += wsum[w];
        g_part[blockIdx.x] = t;
    }
}

// phase 2: single-block scan of block partials -> exclusive block offsets + total
__global__ void scan_block(int nB, int nN) {
    __shared__ int sh[512];
    int t = threadIdx.x;
    int v = (t < nB) ? g_part[t] : 0;
    sh[t] = v;
    __syncthreads();
#pragma unroll
    for (int d = 1; d < 512; d <<= 1) {
        int u = (t >= d) ? sh[t - d] : 0;
        __syncthreads();
        sh[t] += u;
        __syncthreads();
    }
    if (t < nB) g_part[t] = sh[t] - v;   // exclusive offset for block t
    if (t == 511) g_off[nN] = sh[511];   // grand total
}

// phase 3: intra-block exclusive scan + block offset -> g_off / g_pos
__global__ void scan_final(int nN) {
    __shared__ int wsum[8];
    __shared__ int wexcl[8];
    int i = blockIdx.x * 256 + threadIdx.x;
    int lane = threadIdx.x & 31, wid = threadIdx.x >> 5;
    int v = (i < nN) ? g_icnt[i] : 0;
    int x = v;   // inclusive warp scan
#pragma unroll
    for (int d = 1; d < 32; d <<= 1) {
        int u = __shfl_up_sync(0xffffffffu, x, d);
        if (lane >= d) x += u;
    }
    if (lane == 31) wsum[wid] = x;
    __syncthreads();
    if (threadIdx.x == 0) {
        int run = 0;
#pragma unroll
        for (int w = 0; w < 8; ++w) { wexcl[w] = run; run += wsum[w]; }
    }
    __syncthreads();
    if (i < nN) {
        int o = g_part[blockIdx.x] + wexcl[wid] + (x - v);
        g_off[i] = o;
        g_pos[i] = o;
    }
}

__global__ void fill_kernel(const int* __restrict__ src,
                            const int* __restrict__ dst, int nE) {
    int i = blockIdx.x * blockDim.x + threadIdx.x;
    if (i < nE) {
        int p = atomicAdd(&g_pos[dst[i]], 1);
        g_csrc[p] = src[i];
    }
}

// ---------------- pull-mode aggregation: TWO warps per destination node ------
__global__ __launch_bounds__(256)
void gather_kernel(int nN) {
    int w = (blockIdx.x * blockDim.x + threadIdx.x) >> 5;
    int lane = threadIdx.x & 31;
    int node = w >> 1;
    int half = w & 1;
    if (node >= nN) return;
    int beg = g_off[node], end = g_off[node + 1];
    size_t foff = (size_t)half * 128 + lane * 4;
    float4 acc = make_float4(0.f, 0.f, 0.f, 0.f);
    int e = beg;
    for (; e + 3 < end; e += 4) {
        int s0 = g_csrc[e], s1 = g_csrc[e + 1], s2 = g_csrc[e + 2], s3 = g_csrc[e + 3];
        float4 a = *reinterpret_cast<const float4*>(g_h + (size_t)s0 * HIDC + foff);
        float4 b = *reinterpret_cast<const float4*>(g_h + (size_t)s1 * HIDC + foff);
        float4 c = *reinterpret_cast<const float4*>(g_h + (size_t)s2 * HIDC + foff);
        float4 d = *reinterpret_cast<const float4*>(g_h + (size_t)s3 * HIDC + foff);
        acc.x += (a.x + b.x) + (c.x + d.x);
        acc.y += (a.y + b.y) + (c.y + d.y);
        acc.z += (a.z + b.z) + (c.z + d.z);
        acc.w += (a.w + b.w) + (c.w + d.w);
    }
    for (; e < end; ++e) {
        int s0 = g_csrc[e];
        float4 a = *reinterpret_cast<const float4*>(g_h + (size_t)s0 * HIDC + foff);
        acc.x += a.x; acc.y += a.y; acc.z += a.z; acc.w += a.w;
    }
    float inv = 1.f / fmaxf((float)(end - beg), 1.f);
    __nv_bfloat162 hi[2], lo[2];
    split_pair(acc.x * inv, acc.y * inv, hi[0], lo[0]);
    split_pair(acc.z * inv, acc.w * inv, hi[1], lo[1]);
    size_t o = (size_t)node * HIDC + foff;
    *reinterpret_cast<uint2*>(g_mb + o) = *reinterpret_cast<const uint2*>(hi);
    *reinterpret_cast<uint2*>(g_ml + o) = *reinterpret_cast<const uint2*>(lo);
}

// ---------------- consolidated prep: 5 weight-frag sections + x split --------
__device__ void wfrag_one(const float* W, uint2* hi, uint2* lo, int N, int K, int i) {
    int lane = i & 31;
    int rest = i >> 5;
    int n8 = rest % (N / 8);
    int k16 = rest / (N / 8);
    int n = n8 * 8 + (lane >> 2);
    uint32_t rh[2], rl[2];
#pragma unroll
    for (int reg = 0; reg < 2; ++reg) {
        int k = k16 * 16 + reg * 8 + (lane & 3) * 2;
        float w0 = W[(size_t)n * K + k];
        float w1 = W[(size_t)n * K + k + 1];
        __nv_bfloat16 h0 = __float2bfloat16_rn(w0);
        __nv_bfloat16 h1 = __float2bfloat16_rn(w1);
        rh[reg] = ((uint32_t)__bfloat16_as_ushort(h1) << 16) | __bfloat16_as_ushort(h0);
        rl[reg] = ((uint32_t)__bfloat16_as_ushort(__float2bfloat16_rn(w1 - __bfloat162float(h1))) << 16)
                | __bfloat16_as_ushort(__float2bfloat16_rn(w0 - __bfloat162float(h0)));
    }
    hi[i] = make_uint2(rh[0], rh[1]);
    lo[i] = make_uint2(rl[0], rl[1]);
}

__global__ void prep_kernel(const float* __restrict__ x,
                            const float* __restrict__ Win, const float* __restrict__ Wf,
                            const float* __restrict__ Uf, const float* __restrict__ Wh,
                            const float* __restrict__ Uh, int nx) {
    int i = blockIdx.x * blockDim.x + threadIdx.x;
    if (i < 4096) { wfrag_one(Win, g_wih, g_wil, 128, 128, i); return; }
    i -= 4096;
    if (i < 16384) { wfrag_one(Wf, g_wfh, g_wfl, 256, 256, i); return; }
    i -= 16384;
    if (i < 16384) { wfrag_one(Uf, g_ufh, g_ufl, 256, 256, i); return; }
    i -= 16384;
    if (i < 16384) { wfrag_one(Wh, g_whh, g_whl, 256, 256, i); return; }
    i -= 16384;
    if (i < 16384) { wfrag_one(Uh, g_uhh, g_uhl, 256, 256, i); return; }
    i -= 16384;
    int j = i * 2;
    if (j < nx) {
        __nv_bfloat162 hi, lo;
        split_pair(x[j], x[j + 1], hi, lo);
        *reinterpret_cast<__nv_bfloat162*>(g_xb + j) = hi;
        *reinterpret_cast<__nv_bfloat162*>(g_xl + j) = lo;
    }
}

// ---------------- HMMA dual-GEMM (R10 verbatim: 4x2 warp tiling) --------------
__device__ __forceinline__ void mma16816(float c[4], const uint32_t a[4], uint2 b) {
    asm volatile("mma.sync.aligned.m16n8k16.row.col.f32.bf16.bf16.f32 "
                 "{%0,%1,%2,%3}, {%4,%5,%6,%7}, {%8,%9}, {%0,%1,%2,%3};"
                 : "+f"(c[0]), "+f"(c[1]), "+f"(c[2]), "+f"(c[3])
                 : "r"(a[0]), "r"(a[1]), "r"(a[2]), "r"(a[3]), "r"(b.x), "r"(b.y));
}

__global__ __launch_bounds__(256)
void gemm_mma(const __nv_bfloat16* __restrict__ A0h, const __nv_bfloat16* __restrict__ A0l,
              const uint2* __restrict__ W0h, const uint2* __restrict__ W0l, int K0,
              const __nv_bfloat16* __restrict__ A1h, const __nv_bfloat16* __restrict__ A1l,
              const uint2* __restrict__ W1h, const uint2* __restrict__ W1l, int K1,
              int NT, const float* __restrict__ bias, int M, int mode,
              const float* __restrict__ f_in, const float* __restrict__ h_in,
              float* __restrict__ out0,
              __nv_bfloat16* __restrict__ outh, __nv_bfloat16* __restrict__ outl) {
    __shared__ __align__(16) __nv_bfloat16 Ash[128 * 32];
    __shared__ __align__(16) __nv_bfloat16 Asl[128 * 32];

    const int tid = threadIdx.x, lane = tid & 31, warp = tid >> 5;
    const int wm = warp & 3, wn = warp >> 2;
    const int m0 = blockIdx.x * 128;
    const int nblk = blockIdx.y;
    const int nt0 = nblk * 16 + wn * 8;
    const uint32_t sbh = smem_to_u32(Ash);
    const uint32_t sbl = smem_to_u32(Asl);

    float c[2][8][4];
#pragma unroll
    for (int i = 0; i < 2; ++i)
#pragma unroll
        for (int j = 0; j < 8; ++j)
#pragma unroll
            for (int k = 0; k < 4; ++k) c[i][j][k] = 0.f;

    const int lr = lane & 7, lmat = lane >> 3;
    const int lrow_off = (lmat & 1) * 8 + lr;
    const int lcu_off = lmat >> 1;

    for (int pass = 0; pass < 2; ++pass) {
        const __nv_bfloat16* Ah = pass ? A1h : A0h;
        if (!Ah) break;
        const __nv_bfloat16* Al = pass ? A1l : A0l;
        const uint2* Wh = pass ? W1h : W0h;
        const uint2* Wl = pass ? W1l : W0l;
        const int K = pass ? K1 : K0;

        for (int kc = 0; kc < K / 32; ++kc) {
            __syncthreads();
#pragma unroll
            for (int i = 0; i < 2; ++i) {
                int s = tid + i * 256;
                int row = s >> 2, cu = s & 3;
                uint32_t soff = row * 64 + ((cu ^ ((row >> 1) & 3)) << 4);
                uint4 vh = make_uint4(0, 0, 0, 0), vl = make_uint4(0, 0, 0, 0);
                if (m0 + row < M) {
                    size_t go = (size_t)(m0 + row) * K + kc * 32 + cu * 8;
                    vh = *reinterpret_cast<const uint4*>(Ah + go);
                    vl = *reinterpret_cast<const uint4*>(Al + go);
                }
                *reinterpret_cast<uint4*>(reinterpret_cast<char*>(Ash) + soff) = vh;
                *reinterpret_cast<uint4*>(reinterpret_cast<char*>(Asl) + soff) = vl;
            }
            __syncthreads();

#pragma unroll
            for (int k16 = 0; k16 < 2; ++k16) {
                uint32_t ah[2][4], al[2][4];
#pragma unroll
                for (int mt = 0; mt < 2; ++mt) {
                    int row = wm * 32 + mt * 16 + lrow_off;
                    int cu = k16 * 2 + lcu_off;
                    uint32_t soff = row * 64 + ((cu ^ ((row >> 1) & 3)) << 4);
                    asm volatile("ldmatrix.sync.aligned.m8n8.x4.shared.b16 {%0,%1,%2,%3}, [%4];"
                                 : "=r"(ah[mt][0]), "=r"(ah[mt][1]), "=r"(ah[mt][2]), "=r"(ah[mt][3])
                                 : "r"(sbh + soff));
                    asm volatile("ldmatrix.sync.aligned.m8n8.x4.shared.b16 {%0,%1,%2,%3}, [%4];"
                                 : "=r"(al[mt][0]), "=r"(al[mt][1]), "=r"(al[mt][2]), "=r"(al[mt][3])
                                 : "r"(sbl + soff));
                }
                int gk16 = kc * 2 + k16;
                const uint2* bhp = Wh + ((size_t)gk16 * NT + nt0) * 32 + lane;
                const uint2* blp = Wl + ((size_t)gk16 * NT + nt0) * 32 + lane;
#pragma unroll
                for (int nt = 0; nt < 8; ++nt) {
                    uint2 bhv = bhp[nt * 32];
                    uint2 blv = blp[nt * 32];
#pragma unroll
                    for (int mt = 0; mt < 2; ++mt) {
                        mma16816(c[mt][nt], ah[mt], bhv);
                        mma16816(c[mt][nt], ah[mt], blv);
                        mma16816(c[mt][nt], al[mt], bhv);
                    }
                }
            }
        }
    }

    // epilogue
#pragma unroll
    for (int mt = 0; mt < 2; ++mt) {
#pragma unroll
        for (int half = 0; half < 2; ++half) {
            int row = m0 + wm * 32 + mt * 16 + (lane >> 2) + half * 8;
            if (row >= M) continue;
            size_t ro = (size_t)row * HIDC;
#pragma unroll
            for (int nt = 0; nt < 8; ++nt) {
                int col = nblk * 128 + wn * 64 + nt * 8 + (lane & 3) * 2;
                float v0 = c[mt][nt][half * 2 + 0];
                float v1 = c[mt][nt][half * 2 + 1];
                float2 b = *reinterpret_cast<const float2*>(bias + col);
                v0 += b.x; v1 += b.y;
                __nv_bfloat162 hi, lo;
                if (mode == 0) {
                    float o0 = fmaxf(v0, 0.f), o1 = fmaxf(v1, 0.f);
                    *reinterpret_cast<float2*>(out0 + ro + col) = make_float2(o0, o1);
                    split_pair(o0, o1, hi, lo);
                } else if (mode == 1) {
                    float f0 = 1.f / (1.f + expf(-v0));
                    float f1 = 1.f / (1.f + expf(-v1));
                    float2 h = *reinterpret_cast<const float2*>(h_in + ro + col);
                    *reinterpret_cast<float2*>(out0 + ro + col) = make_float2(f0, f1);
                    split_pair(f0 * h.x, f1 * h.y, hi, lo);
                } else {
                    float t0 = tanhf(v0), t1 = tanhf(v1);
                    float2 f = *reinterpret_cast<const float2*>(f_in + ro + col);
                    float2 h = *reinterpret_cast<const float2*>(h_in + ro + col);
                    float o0 = (1.f - f.x) * h.x + f.x * t0;
                    float o1 = (1.f - f.y) * h.y + f.y * t1;
                    *reinterpret_cast<float2*>(out0 + ro + col) = make_float2(o0, o1);
                    split_pair(o0, o1, hi, lo);
                }
                *reinterpret_cast<__nv_bfloat162*>(outh + ro + col) = hi;
                *reinterpret_cast<__nv_bfloat162*>(outl + ro + col) = lo;
            }
        }
    }
}

// ---------------- readout ----------------
__global__ void colsum_kernel(int nN) {
    int t = threadIdx.x;
    float acc = 0.f;
    for (int r = blockIdx.x; r < nN; r += gridDim.x)
        acc += g_h[(size_t)r * HIDC + t];
    atomicAdd(&g_sum[t], acc);
}
__global__ void final_kernel(const float* __restrict__ Wp, const float* __restrict__ bp,
                             float* __restrict__ out, int nN) {
    __shared__ float sh[HIDC];
    int t = threadIdx.x;
    sh[t] = g_sum[t] * (1.0f / (float)nN) * Wp[t];
    __syncthreads();
    for (int s = 128; s > 0; s >>= 1) {
        if (t < s) sh[t] += sh[t + s];
        __syncthreads();
    }
    if (t == 0) out[0] = sh[0] + bp[0];
}

// ---------------- launch ----------------
extern "C" void kernel_launch(void* const* d_in, const int* in_sizes, int n_in,
                              void* d_out, int out_size) {
    const float* x      = (const float*)d_in[0];
    const int*   ei     = (const int*)d_in[1];   // int32 (jax x64 disabled)
    const float* b_in   = (const float*)d_in[3];
    const float* b_f    = (const float*)d_in[6];
    const float* b_h    = (const float*)d_in[9];
    const float* W_pred = (const float*)d_in[10];
    const float* b_pred = (const float*)d_in[11];
    float* out = (float*)d_out;

    int nN = in_sizes[0] / INFEAT;   // 100000
    int nE = in_sizes[1] / 2;        // 3200000
    const int* srcp = ei;
    const int* dstp = ei + nE;

    void *ph, *pf, *phb, *phl, *pfhb, *pfhl, *pmb, *pml, *pxb, *pxl, *picnt, *psum;
    void *pwih, *pwil, *pwfh, *pwfl, *pufh, *pufl, *pwhh, *pwhl, *puhh, *puhl;
    cudaGetSymbolAddress(&ph, g_h);
    cudaGetSymbolAddress(&pf, g_f);
    cudaGetSymbolAddress(&phb, g_hb);   cudaGetSymbolAddress(&phl, g_hl);
    cudaGetSymbolAddress(&pfhb, g_fhb); cudaGetSymbolAddress(&pfhl, g_fhl);
    cudaGetSymbolAddress(&pmb, g_mb);   cudaGetSymbolAddress(&pml, g_ml);
    cudaGetSymbolAddress(&pxb, g_xb);   cudaGetSymbolAddress(&pxl, g_xl);
    cudaGetSymbolAddress(&picnt, g_icnt);
    cudaGetSymbolAddress(&psum, g_sum);
    cudaGetSymbolAddress(&pwih, g_wih); cudaGetSymbolAddress(&pwil, g_wil);
    cudaGetSymbolAddress(&pwfh, g_wfh); cudaGetSymbolAddress(&pwfl, g_wfl);
    cudaGetSymbolAddress(&pufh, g_ufh); cudaGetSymbolAddress(&pufl, g_ufl);
    cudaGetSymbolAddress(&pwhh, g_whh); cudaGetSymbolAddress(&pwhl, g_whl);
    cudaGetSymbolAddress(&puhh, g_uhh); cudaGetSymbolAddress(&puhl, g_uhl);
    float* hbuf = (float*)ph;
    float* fbuf = (float*)pf;
    __nv_bfloat16 *hb = (__nv_bfloat16*)phb,  *hl = (__nv_bfloat16*)phl;
    __nv_bfloat16 *fhb = (__nv_bfloat16*)pfhb, *fhl = (__nv_bfloat16*)pfhl;
    __nv_bfloat16 *mb = (__nv_bfloat16*)pmb,  *ml = (__nv_bfloat16*)pml;

    size_t hbytes = (size_t)nN * HIDC * sizeof(float);
    size_t bbytes = (size_t)nN * HIDC * sizeof(__nv_bfloat16);

    cudaMemsetAsync(ph, 0, hbytes);
    cudaMemsetAsync(phb, 0, bbytes);
    cudaMemsetAsync(phl, 0, bbytes);
    cudaMemsetAsync(picnt, 0, (size_t)nN * sizeof(int));

    // launch 1: prep (weights + x split)
    int prep_threads = 4096 + 4 * 16384 + nN * INFEAT / 2;
    prep_kernel<<<(prep_threads + 255) / 256, 256>>>(
        x, (const float*)d_in[2], (const float*)d_in[4], (const float*)d_in[5],
        (const float*)d_in[7], (const float*)d_in[8], nN * INFEAT);

    int gmx = (nN + 127) / 128;
    // launch 2: encode GEMM
    gemm_mma<<<dim3(gmx, 1), 256>>>(
        (__nv_bfloat16*)pxb, (__nv_bfloat16*)pxl, (uint2*)pwih, (uint2*)pwil, INFEAT,
        nullptr, nullptr, nullptr, nullptr, 0, 16,
        b_in, nN, 0, nullptr, nullptr, hbuf, hb, hl);

    // launches 3-7: CSR build (multi-block scan)
    int nB = (nN + 255) / 256;    // 391 blocks <= 512
    count_kernel<<<(nE + 255) / 256, 256>>>(dstp, nE);
    scan_partial<<<nB, 256>>>(nN);
    scan_block<<<1, 512>>>(nB, nN);
    scan_final<<<nB, 256>>>(nN);
    fill_kernel<<<(nE + 255) / 256, 256>>>(srcp, dstp, nE);

    // mainloop
    int gather_blocks = (2 * nN + 7) / 8;   // 2 warps/node
    for (int step = 0; step < 4; ++step) {
        gather_kernel<<<gather_blocks, 256>>>(nN);
        gemm_mma<<<dim3(gmx, 2), 256>>>(
            mb, ml, (uint2*)pwfh, (uint2*)pwfl, HIDC,
            hb, hl, (uint2*)pufh, (uint2*)pufl, HIDC, 32,
            b_f, nN, 1, nullptr, hbuf, fbuf, fhb, fhl);
        gemm_mma<<<dim3(gmx, 2), 256>>>(
            mb, ml, (uint2*)pwhh, (uint2*)pwhl, HIDC,
            fhb, fhl, (uint2*)puhh, (uint2*)puhl, HIDC, 32,
            b_h, nN, 2, fbuf, hbuf, hbuf, hb, hl);
    }

    cudaMemsetAsync(psum, 0, HIDC * sizeof(float));
    colsum_kernel<<<1024, 256>>>(nN);
    final_kernel<<<1, 256>>>(W_pred, b_pred, out, nN);
}